// round 2
// baseline (speedup 1.0000x reference)
#include <cuda_runtime.h>

// VectorQuantizer: x [32,2048,64] f32, codebook [1024,64] f32
// outputs concatenated f32: quantized [32,64,2048] (4194304) | loss (1) | indices [32,2048] (65536)

#define N_TOK   (32 * 2048)
#define K_CODES 1024
#define D_DIM   64
#define T_LEN   2048
#define BDIM    128
#define CHUNK   128
#define NCHUNK  (K_CODES / CHUNK)

#define LOSS_OFF ((size_t)N_TOK * D_DIM)       // 4194304
#define IDX_OFF  (LOSS_OFF + 1)                // 4194305

__device__ double g_loss_acc;
__device__ float  g_bsq[K_CODES];

__global__ void vq_init_kernel() { g_loss_acc = 0.0; }

// B_k = sum(e_k^2), sequential fp32 mul-then-add (mimic jnp.sum(cb*cb, axis=1))
__global__ void vq_bsq_kernel(const float* __restrict__ cb) {
    int k = blockIdx.x * blockDim.x + threadIdx.x;
    if (k >= K_CODES) return;
    float s = 0.0f;
    const float* row = cb + (size_t)k * D_DIM;
    #pragma unroll 8
    for (int i = 0; i < D_DIM; i++) {
        s = __fadd_rn(s, __fmul_rn(row[i], row[i]));
    }
    g_bsq[k] = s;
}

__global__ __launch_bounds__(BDIM) void vq_main_kernel(
    const float4* __restrict__ x4,
    const float4* __restrict__ cb4,
    float* __restrict__ out)
{
    __shared__ float4 sE[CHUNK * 16];   // 128 codes x 64 floats = 32 KB
    __shared__ float  sB[CHUNK];

    const int tok = blockIdx.x * BDIM + threadIdx.x;   // grid sized exactly

    // ---- load x row into registers (16 x float4 = 64 floats) ----
    float4 xr[16];
    #pragma unroll
    for (int j = 0; j < 16; j++) xr[j] = x4[(size_t)tok * 16 + j];

    // ---- A = sum(x^2), sequential fp32, explicit mul-then-add rounding ----
    float A = 0.0f;
    #pragma unroll
    for (int j = 0; j < 16; j++) {
        A = __fadd_rn(A, __fmul_rn(xr[j].x, xr[j].x));
        A = __fadd_rn(A, __fmul_rn(xr[j].y, xr[j].y));
        A = __fadd_rn(A, __fmul_rn(xr[j].z, xr[j].z));
        A = __fadd_rn(A, __fmul_rn(xr[j].w, xr[j].w));
    }

    float best = 3.402823466e38f;
    int   bidx = 0;

    for (int ch = 0; ch < NCHUNK; ch++) {
        __syncthreads();
        // cooperative chunk load: 2048 float4, 16 per thread, coalesced
        #pragma unroll
        for (int i = 0; i < 16; i++) {
            sE[threadIdx.x + i * BDIM] = cb4[(size_t)ch * (CHUNK * 16) + threadIdx.x + i * BDIM];
        }
        sB[threadIdx.x] = g_bsq[ch * CHUNK + threadIdx.x];
        __syncthreads();

        #pragma unroll 2
        for (int c = 0; c < CHUNK; c++) {
            const float4* e = sE + c * 16;   // broadcast across warp: conflict-free
            float a0 = 0.f, a1 = 0.f, a2 = 0.f, a3 = 0.f;
            #pragma unroll
            for (int j = 0; j < 16; j++) {
                float4 ev = e[j];
                float4 xv = xr[j];
                a0 = fmaf(xv.x, ev.x, a0);
                a1 = fmaf(xv.y, ev.y, a1);
                a2 = fmaf(xv.z, ev.z, a2);
                a3 = fmaf(xv.w, ev.w, a3);
            }
            float dot = __fadd_rn(__fadd_rn(a0, a1), __fadd_rn(a2, a3));
            // replicate reference rounding: t = fl(A + B_k); d = fl(t - 2*dot)
            float t = __fadd_rn(A, sB[c]);
            float d = __fadd_rn(t, -__fmul_rn(2.0f, dot));
            if (d < best) { best = d; bidx = ch * CHUNK + c; }   // first-index tie-break
        }
    }

    // ---- epilogue: quantized (transposed), loss contribution, index ----
    const int b = tok >> 11;          // /2048
    const int t = tok & 2047;
    float* qout = out + ((size_t)b * D_DIM) * T_LEN + t;
    const float4* e = cb4 + (size_t)bidx * 16;

    double ls = 0.0;
    #pragma unroll
    for (int j = 0; j < 16; j++) {
        float4 ev = e[j];
        float4 xv = xr[j];
        // straight-through value: q_out = fl(x + fl(q - x)), loss diff = fl(q - x)
        float d0 = __fadd_rn(ev.x, -xv.x);
        float d1 = __fadd_rn(ev.y, -xv.y);
        float d2 = __fadd_rn(ev.z, -xv.z);
        float d3 = __fadd_rn(ev.w, -xv.w);
        ls += (double)d0 * d0 + (double)d1 * d1 + (double)d2 * d2 + (double)d3 * d3;
        qout[(size_t)(4 * j + 0) * T_LEN] = __fadd_rn(xv.x, d0);
        qout[(size_t)(4 * j + 1) * T_LEN] = __fadd_rn(xv.y, d1);
        qout[(size_t)(4 * j + 2) * T_LEN] = __fadd_rn(xv.z, d2);
        qout[(size_t)(4 * j + 3) * T_LEN] = __fadd_rn(xv.w, d3);
    }

    out[IDX_OFF + tok] = (float)bidx;

    // warp-reduce loss, one atomic per warp
    #pragma unroll
    for (int o = 16; o > 0; o >>= 1)
        ls += __shfl_down_sync(0xffffffffu, ls, o);
    if ((threadIdx.x & 31) == 0)
        atomicAdd(&g_loss_acc, ls);
}

__global__ void vq_finalize_kernel(float* __restrict__ out) {
    double m = g_loss_acc / (double)((size_t)N_TOK * D_DIM);
    out[LOSS_OFF] = (float)(m + 0.25 * m);
}

extern "C" void kernel_launch(void* const* d_in, const int* in_sizes, int n_in,
                              void* d_out, int out_size) {
    const float*  x   = (const float*)d_in[0];
    const float*  cb  = (const float*)d_in[1];
    float* out = (float*)d_out;
    (void)in_sizes; (void)n_in; (void)out_size;

    vq_init_kernel<<<1, 1>>>();
    vq_bsq_kernel<<<(K_CODES + 127) / 128, 128>>>(cb);
    vq_main_kernel<<<N_TOK / BDIM, BDIM>>>((const float4*)x, (const float4*)cb, out);
    vq_finalize_kernel<<<1, 1>>>(out);
}

// round 3
// speedup vs baseline: 1.0872x; 1.0872x over previous
#include <cuda_runtime.h>

// VectorQuantizer: x [32,2048,64] f32, codebook [1024,64] f32
// outputs concatenated f32: quantized [32,64,2048] (4194304) | loss (1) | indices [32,2048] (65536)

#define N_TOK   (32 * 2048)
#define K_CODES 1024
#define D_DIM   64
#define T_LEN   2048
#define BDIM    128
#define CHUNK   128
#define NCHUNK  (K_CODES / CHUNK)

#define LOSS_OFF ((size_t)N_TOK * D_DIM)       // 4194304
#define IDX_OFF  (LOSS_OFF + 1)                // 4194305

__device__ double g_loss_acc;
__device__ float  g_bsq[K_CODES];

__global__ void vq_init_kernel() { g_loss_acc = 0.0; }

// B_k = sum(e_k^2), sequential fp32 mul-then-add (mimic jnp.sum(cb*cb, axis=1))
__global__ void vq_bsq_kernel(const float* __restrict__ cb) {
    int k = blockIdx.x * blockDim.x + threadIdx.x;
    if (k >= K_CODES) return;
    float s = 0.0f;
    const float* row = cb + (size_t)k * D_DIM;
    #pragma unroll 8
    for (int i = 0; i < D_DIM; i++) {
        s = __fadd_rn(s, __fmul_rn(row[i], row[i]));
    }
    g_bsq[k] = s;
}

// packed fp32x2 FMA: two independent rn-rounded fp32 FMAs in one instruction (FFMA2)
#define FMA2(acc, a, b) \
    asm("fma.rn.f32x2 %0, %1, %2, %3;" : "=l"(acc) : "l"(a), "l"(b), "l"(acc))

__device__ __forceinline__ float lo32(unsigned long long u) {
    return __uint_as_float((unsigned)u);
}
__device__ __forceinline__ float hi32(unsigned long long u) {
    return __uint_as_float((unsigned)(u >> 32));
}

__global__ __launch_bounds__(BDIM) void vq_main_kernel(
    const float4* __restrict__ x4,
    const float4* __restrict__ cb4,
    float* __restrict__ out)
{
    __shared__ float4 sE[CHUNK * 16];   // 128 codes x 64 floats = 32 KB
    __shared__ float  sB[CHUNK];

    const int tok = blockIdx.x * BDIM + threadIdx.x;   // grid sized exactly

    // ---- load x row packed: 16 x ulonglong2 = 32 x u64 = 64 floats ----
    unsigned long long xu[32];
    {
        const ulonglong2* xg = reinterpret_cast<const ulonglong2*>(x4 + (size_t)tok * 16);
        #pragma unroll
        for (int j = 0; j < 16; j++) {
            ulonglong2 v = xg[j];
            xu[2 * j]     = v.x;   // (x, y) of float4 j
            xu[2 * j + 1] = v.y;   // (z, w) of float4 j
        }
    }

    // ---- A = sum(x^2), sequential fp32, explicit mul-then-add rounding ----
    float A = 0.0f;
    #pragma unroll
    for (int p = 0; p < 32; p++) {
        float fl_ = lo32(xu[p]);
        float fh_ = hi32(xu[p]);
        A = __fadd_rn(A, __fmul_rn(fl_, fl_));
        A = __fadd_rn(A, __fmul_rn(fh_, fh_));
    }

    float best = 3.402823466e38f;
    int   bidx = 0;

    for (int ch = 0; ch < NCHUNK; ch++) {
        __syncthreads();
        // cooperative chunk load: 2048 float4, 16 per thread, coalesced
        #pragma unroll
        for (int i = 0; i < 16; i++) {
            sE[threadIdx.x + i * BDIM] = cb4[(size_t)ch * (CHUNK * 16) + threadIdx.x + i * BDIM];
        }
        sB[threadIdx.x] = g_bsq[ch * CHUNK + threadIdx.x];
        __syncthreads();

        #pragma unroll 2
        for (int c = 0; c < CHUNK; c++) {
            const ulonglong2* e2 = reinterpret_cast<const ulonglong2*>(sE + c * 16);
            unsigned long long acc01 = 0ull;   // lanes (a0, a1)
            unsigned long long acc23 = 0ull;   // lanes (a2, a3)
            #pragma unroll
            for (int j = 0; j < 16; j++) {
                ulonglong2 ev = e2[j];         // LDS.128, warp-broadcast
                FMA2(acc01, xu[2 * j],     ev.x);
                FMA2(acc23, xu[2 * j + 1], ev.y);
            }
            // identical combine to scalar version: fl(fl(a0+a1)+fl(a2+a3))
            float dot = __fadd_rn(__fadd_rn(lo32(acc01), hi32(acc01)),
                                  __fadd_rn(lo32(acc23), hi32(acc23)));
            // replicate reference rounding: t = fl(A + B_k); d = fl(t - 2*dot)
            float t = __fadd_rn(A, sB[c]);
            float d = __fadd_rn(t, -__fmul_rn(2.0f, dot));
            if (d < best) { best = d; bidx = ch * CHUNK + c; }   // first-index tie-break
        }
    }

    // ---- epilogue: quantized (transposed), loss contribution, index ----
    const int b = tok >> 11;          // /2048
    const int t = tok & 2047;
    float* qout = out + ((size_t)b * D_DIM) * T_LEN + t;
    const ulonglong2* eg = reinterpret_cast<const ulonglong2*>(cb4 + (size_t)bidx * 16);

    double ls = 0.0;
    #pragma unroll
    for (int j = 0; j < 16; j++) {
        ulonglong2 ev = eg[j];
        float e0 = lo32(ev.x), e1 = hi32(ev.x), e2v = lo32(ev.y), e3 = hi32(ev.y);
        float x0 = lo32(xu[2 * j]),     x1 = hi32(xu[2 * j]);
        float x2 = lo32(xu[2 * j + 1]), x3 = hi32(xu[2 * j + 1]);
        // straight-through value: q_out = fl(x + fl(q - x)), loss diff = fl(q - x)
        float d0 = __fadd_rn(e0, -x0);
        float d1 = __fadd_rn(e1, -x1);
        float d2 = __fadd_rn(e2v, -x2);
        float d3 = __fadd_rn(e3, -x3);
        ls += (double)d0 * d0 + (double)d1 * d1 + (double)d2 * d2 + (double)d3 * d3;
        qout[(size_t)(4 * j + 0) * T_LEN] = __fadd_rn(x0, d0);
        qout[(size_t)(4 * j + 1) * T_LEN] = __fadd_rn(x1, d1);
        qout[(size_t)(4 * j + 2) * T_LEN] = __fadd_rn(x2, d2);
        qout[(size_t)(4 * j + 3) * T_LEN] = __fadd_rn(x3, d3);
    }

    out[IDX_OFF + tok] = (float)bidx;

    // warp-reduce loss, one atomic per warp
    #pragma unroll
    for (int o = 16; o > 0; o >>= 1)
        ls += __shfl_down_sync(0xffffffffu, ls, o);
    if ((threadIdx.x & 31) == 0)
        atomicAdd(&g_loss_acc, ls);
}

__global__ void vq_finalize_kernel(float* __restrict__ out) {
    double m = g_loss_acc / (double)((size_t)N_TOK * D_DIM);
    out[LOSS_OFF] = (float)(m + 0.25 * m);
}

extern "C" void kernel_launch(void* const* d_in, const int* in_sizes, int n_in,
                              void* d_out, int out_size) {
    const float*  x   = (const float*)d_in[0];
    const float*  cb  = (const float*)d_in[1];
    float* out = (float*)d_out;
    (void)in_sizes; (void)n_in; (void)out_size;

    vq_init_kernel<<<1, 1>>>();
    vq_bsq_kernel<<<(K_CODES + 127) / 128, 128>>>(cb);
    vq_main_kernel<<<N_TOK / BDIM, BDIM>>>((const float4*)x, (const float4*)cb, out);
    vq_finalize_kernel<<<1, 1>>>(out);
}